// round 1
// baseline (speedup 1.0000x reference)
#include <cuda_runtime.h>
#include <cstdint>

// Problem constants
#define BS_ROWS   1024          // B*S = 4*256
#define VOCAB     50257
#define DMODEL    768
#define TOTAL_ELEMS (BS_ROWS * (long long)VOCAB)   // 51,463,168 (divisible by 4)
#define TOTAL_F4    (TOTAL_ELEMS / 4)              // 12,865,792

// Scratch: per-row nonzero column index and value (allocation-free rule: __device__ globals)
__device__ int   g_idx[BS_ROWS];
__device__ float g_val[BS_ROWS];

// ---------------------------------------------------------------------------
// Kernel A: streaming scan of the one-hot tensor to find each row's nonzero.
// Grid-stride over float4s; the nonzero branch fires once per ~50K elements.
// ---------------------------------------------------------------------------
__global__ void __launch_bounds__(256) find_nonzeros_kernel(const float4* __restrict__ oh4)
{
    const long long stride = (long long)gridDim.x * blockDim.x;
    long long i = (long long)blockIdx.x * blockDim.x + threadIdx.x;

    // 4-way unrolled grid-stride loop for MLP; predicated check per vector.
    for (; i + 3 * stride < TOTAL_F4; i += 4 * stride) {
        float4 a = __ldg(&oh4[i]);
        float4 b = __ldg(&oh4[i + stride]);
        float4 c = __ldg(&oh4[i + 2 * stride]);
        float4 d = __ldg(&oh4[i + 3 * stride]);

        #pragma unroll
        for (int u = 0; u < 4; u++) {
            float4 v = (u == 0) ? a : (u == 1) ? b : (u == 2) ? c : d;
            long long base = (i + (long long)u * stride) * 4;
            if (v.x != 0.0f || v.y != 0.0f || v.z != 0.0f || v.w != 0.0f) {
                float vals[4] = {v.x, v.y, v.z, v.w};
                #pragma unroll
                for (int k = 0; k < 4; k++) {
                    if (vals[k] != 0.0f) {
                        long long g = base + k;
                        int row = (int)(g / VOCAB);
                        int col = (int)(g - (long long)row * VOCAB);
                        g_idx[row] = col;
                        g_val[row] = vals[k];
                    }
                }
            }
        }
    }
    // Tail
    for (; i < TOTAL_F4; i += stride) {
        float4 v = __ldg(&oh4[i]);
        if (v.x != 0.0f || v.y != 0.0f || v.z != 0.0f || v.w != 0.0f) {
            float vals[4] = {v.x, v.y, v.z, v.w};
            long long base = i * 4;
            #pragma unroll
            for (int k = 0; k < 4; k++) {
                if (vals[k] != 0.0f) {
                    long long g = base + k;
                    int row = (int)(g / VOCAB);
                    int col = (int)(g - (long long)row * VOCAB);
                    g_idx[row] = col;
                    g_val[row] = vals[k];
                }
            }
        }
    }
}

// ---------------------------------------------------------------------------
// Kernel B: gather — out[row, :] = val[row] * weight[idx[row], :]
// One block per row, 192 threads, one float4 each (768 floats / row).
// ---------------------------------------------------------------------------
__global__ void __launch_bounds__(192) gather_kernel(const float4* __restrict__ w4,
                                                     float4* __restrict__ out4)
{
    const int row = blockIdx.x;
    const int t   = threadIdx.x;           // 0..191
    const int idx = g_idx[row];
    const float v = g_val[row];

    float4 a = __ldg(&w4[(long long)idx * (DMODEL / 4) + t]);
    a.x *= v; a.y *= v; a.z *= v; a.w *= v;
    out4[(long long)row * (DMODEL / 4) + t] = a;
}

// ---------------------------------------------------------------------------
extern "C" void kernel_launch(void* const* d_in, const int* in_sizes, int n_in,
                              void* d_out, int out_size)
{
    // Identify inputs by element count (robust to ordering).
    const float* one_hot = nullptr;
    const float* weight  = nullptr;
    for (int i = 0; i < n_in; i++) {
        if (in_sizes[i] == (int)TOTAL_ELEMS)            one_hot = (const float*)d_in[i];
        else if (in_sizes[i] == VOCAB * DMODEL)         weight  = (const float*)d_in[i];
    }

    // Kernel A: saturate HBM with the scan. 148 SMs, plenty of waves.
    const int threadsA = 256;
    const int blocksA  = 148 * 16;   // 2368 blocks -> ~21 f4 iters/thread
    find_nonzeros_kernel<<<blocksA, threadsA>>>((const float4*)one_hot);

    // Kernel B: gather.
    gather_kernel<<<BS_ROWS, 192>>>((const float4*)weight, (float4*)d_out);
}